// round 2
// baseline (speedup 1.0000x reference)
#include <cuda_runtime.h>

// ---------------------------------------------------------------------------
// Bicubic downsample 768x768 -> 384x384, scale exactly 0.5.
//
// Reference math collapses: tap offsets are constant across all output
// positions, so the normalized separable weights are the fixed vector
//   wn = {-9, 29, 111, 111, 29, -9} / 262      (sum of numerators = 262)
// and the 36-entry 2D weight matrix (second output tensor) is the constant
//   pat[p][q] = a_p * a_q / 68644,  a in {-9,29,111,111,29,-9}, 68644 = 262^2
// tiled over (B=4, 384, 384). Gather rows/cols: clamp(2*o - 2 + tap, 0, 767).
// ---------------------------------------------------------------------------

#define IN_H   768
#define IN_W   768
#define OUT_H  384
#define OUT_W  384
#define BC     12                          // B*C = 4*3
#define RES_ELEMS (BC * OUT_H * OUT_W)     // 1,769,472
#define KER_ELEMS (4 * OUT_H * OUT_W * 36) // 21,233,664
#define N4        (KER_ELEMS / 4)          // 5,308,416  (36 % 4 == 0, no wrap)

// Separable normalized weights (exact rationals; float-rounded identically
// to the float32 reference computation).
#define WN0 ((float)(-9.0  / 262.0))
#define WN1 ((float)(29.0  / 262.0))
#define WN2 ((float)(111.0 / 262.0))

// 2D weight pattern numerators
#define AD(p) ((p)==0 ? -9.0 : (p)==1 ? 29.0 : (p)==2 ? 111.0 : \
               (p)==3 ? 111.0 : (p)==4 ? 29.0 : -9.0)
#define PW(p,q) ((float)(AD(p) * AD(q) / 68644.0))
#define PROW(p) PW(p,0), PW(p,1), PW(p,2), PW(p,3), PW(p,4), PW(p,5)

__device__ __constant__ float g_pat[36] = {
    PROW(0), PROW(1), PROW(2), PROW(3), PROW(4), PROW(5)
};

// ---------------------------------------------------------------------------
// Kernel A: the resize. One thread per output pixel.
// Interior columns use float2 loads (2j-2 is even -> 8B aligned).
// ---------------------------------------------------------------------------
__global__ __launch_bounds__(128) void resize_kernel(
    const float* __restrict__ in, float* __restrict__ out)
{
    const int j  = blockIdx.x * blockDim.x + threadIdx.x; // 0..383
    const int i  = blockIdx.y;                            // 0..383
    const int bc = blockIdx.z;                            // 0..11

    const float wn[6] = {WN0, WN1, WN2, WN2, WN1, WN0};
    const float* base = in + (size_t)bc * (IN_H * IN_W);

    const int r0 = 2 * i - 2;
    float acc = 0.0f;

    if (j >= 1 && j < OUT_W - 1) {
        // interior columns: 2j-2 .. 2j+3, no clamping needed, vectorize
        const int c0 = 2 * j - 2;
        #pragma unroll
        for (int p = 0; p < 6; p++) {
            int r = r0 + p;
            r = r < 0 ? 0 : (r > IN_H - 1 ? IN_H - 1 : r);
            const float* row = base + r * IN_W + c0;
            const float2 a = *reinterpret_cast<const float2*>(row);
            const float2 b = *reinterpret_cast<const float2*>(row + 2);
            const float2 c = *reinterpret_cast<const float2*>(row + 4);
            float h = wn[0] * a.x;
            h = fmaf(wn[1], a.y, h);
            h = fmaf(wn[2], b.x, h);
            h = fmaf(wn[3], b.y, h);
            h = fmaf(wn[4], c.x, h);
            h = fmaf(wn[5], c.y, h);
            acc = fmaf(wn[p], h, acc);
        }
    } else {
        // border columns: scalar loads with clamping
        const int c0 = 2 * j - 2;
        #pragma unroll
        for (int p = 0; p < 6; p++) {
            int r = r0 + p;
            r = r < 0 ? 0 : (r > IN_H - 1 ? IN_H - 1 : r);
            const float* row = base + r * IN_W;
            float h = 0.0f;
            #pragma unroll
            for (int q = 0; q < 6; q++) {
                int cc = c0 + q;
                cc = cc < 0 ? 0 : (cc > IN_W - 1 ? IN_W - 1 : cc);
                h = fmaf(wn[q], row[cc], h);
            }
            acc = fmaf(wn[p], h, acc);
        }
    }

    out[((size_t)bc * OUT_H + i) * OUT_W + j] = acc;
}

// ---------------------------------------------------------------------------
// Kernel B: tile the constant 36-float weight pattern into the second output.
// 36 floats == 9 float4; float4 index % 9 selects a 16B-aligned smem chunk.
// Fully coalesced STG.128.
// ---------------------------------------------------------------------------
__global__ __launch_bounds__(256) void fill_kernel(float4* __restrict__ outk)
{
    __shared__ __align__(16) float spat[36];
    const int t = threadIdx.x;
    if (t < 36) spat[t] = g_pat[t];
    __syncthreads();

    const int idx = blockIdx.x * 256 + t;   // grid sized exactly: N4 / 256
    const int r = idx % 9;
    outk[idx] = *reinterpret_cast<const float4*>(spat + r * 4);
}

// ---------------------------------------------------------------------------
extern "C" void kernel_launch(void* const* d_in, const int* in_sizes, int n_in,
                              void* d_out, int out_size)
{
    const float* in = (const float*)d_in[0];
    float* out = (float*)d_out;

    // Output layout: res (12*384*384 floats) followed by kernel weights
    // (4*384*384*36 floats), per reference tuple order.
    dim3 grid_a(OUT_W / 128, OUT_H, BC);
    resize_kernel<<<grid_a, 128>>>(in, out);

    fill_kernel<<<N4 / 256, 256>>>(
        reinterpret_cast<float4*>(out + RES_ELEMS));
}

// round 3
// speedup vs baseline: 1.1759x; 1.1759x over previous
#include <cuda_runtime.h>

// ---------------------------------------------------------------------------
// Bicubic downsample 768x768 -> 384x384 (scale exactly 0.5) + constant
// 36-weight pattern tiled into the second output. Single fused launch.
//
//   wn  = {-9, 29, 111, 111, 29, -9} / 262
//   pat = a_p*a_q / 68644
//   gather rows/cols: clamp(2*o - 2 + tap, 0, 767)
// ---------------------------------------------------------------------------

#define IN_H   768
#define IN_W   768
#define OUT_H  384
#define OUT_W  384
#define BC     12
#define RES_ELEMS (BC * OUT_H * OUT_W)       // 1,769,472
#define KER_ELEMS (4 * OUT_H * OUT_W * 36)   // 21,233,664
#define N4        (KER_ELEMS / 4)            // 5,308,416
#define FILL_K    16
#define FILL_T    (N4 / FILL_K)              // 331,776 (multiple of 9)
#define FILL_BLOCKS (FILL_T / 256)           // 1296
#define STRIP     8
#define NSTRIPS   (OUT_H / STRIP)            // 48
#define RES_WORK  (BC * NSTRIPS * OUT_W)     // 221,184
#define RES_BLOCKS (RES_WORK / 256)          // 864

#define WN0 ((float)(-9.0  / 262.0))
#define WN1 ((float)(29.0  / 262.0))
#define WN2 ((float)(111.0 / 262.0))

#define AD(p) ((p)==0 ? -9.0 : (p)==1 ? 29.0 : (p)==2 ? 111.0 : \
               (p)==3 ? 111.0 : (p)==4 ? 29.0 : -9.0)
#define PW(p,q) ((float)(AD(p) * AD(q) / 68644.0))
#define PROW(p) PW(p,0), PW(p,1), PW(p,2), PW(p,3), PW(p,4), PW(p,5)

__device__ __constant__ __align__(16) float g_pat[36] = {
    PROW(0), PROW(1), PROW(2), PROW(3), PROW(4), PROW(5)
};

// Horizontally filter input row r (clamped) at output column j.
template <bool INTERIOR>
__device__ __forceinline__ float hfilt(const float* __restrict__ base,
                                       int r, int j)
{
    r = r < 0 ? 0 : (r > IN_H - 1 ? IN_H - 1 : r);
    const float* row = base + r * IN_W;
    const int c0 = 2 * j - 2;
    if (INTERIOR) {
        const float2 a = *reinterpret_cast<const float2*>(row + c0);
        const float2 b = *reinterpret_cast<const float2*>(row + c0 + 2);
        const float2 c = *reinterpret_cast<const float2*>(row + c0 + 4);
        float h = WN0 * a.x;
        h = fmaf(WN1, a.y, h);
        h = fmaf(WN2, b.x, h);
        h = fmaf(WN2, b.y, h);
        h = fmaf(WN1, c.x, h);
        h = fmaf(WN0, c.y, h);
        return h;
    } else {
        const float w[6] = {WN0, WN1, WN2, WN2, WN1, WN0};
        float h = 0.0f;
        #pragma unroll
        for (int q = 0; q < 6; q++) {
            int cc = c0 + q;
            cc = cc < 0 ? 0 : (cc > IN_W - 1 ? IN_W - 1 : cc);
            h = fmaf(w[q], row[cc], h);
        }
        return h;
    }
}

// 8 output rows per thread with a rolling window of h-filtered rows.
template <bool INTERIOR>
__device__ __forceinline__ void resize_strip(const float* __restrict__ base,
                                             float* __restrict__ dst,
                                             int i0, int j)
{
    const int r0 = 2 * i0 - 2;
    float h0 = hfilt<INTERIOR>(base, r0 + 0, j);
    float h1 = hfilt<INTERIOR>(base, r0 + 1, j);
    float h2 = hfilt<INTERIOR>(base, r0 + 2, j);
    float h3 = hfilt<INTERIOR>(base, r0 + 3, j);
    float h4 = hfilt<INTERIOR>(base, r0 + 4, j);
    float h5 = hfilt<INTERIOR>(base, r0 + 5, j);

    #pragma unroll
    for (int ii = 0; ii < STRIP; ii++) {
        float acc = WN0 * h0;
        acc = fmaf(WN1, h1, acc);
        acc = fmaf(WN2, h2, acc);
        acc = fmaf(WN2, h3, acc);
        acc = fmaf(WN1, h4, acc);
        acc = fmaf(WN0, h5, acc);
        dst[(i0 + ii) * OUT_W + j] = acc;
        if (ii < STRIP - 1) {
            h0 = h2; h1 = h3; h2 = h4; h3 = h5;
            const int rn = 2 * (i0 + ii + 1) + 2;
            h4 = hfilt<INTERIOR>(base, rn,     j);
            h5 = hfilt<INTERIOR>(base, rn + 1, j);
        }
    }
}

__global__ __launch_bounds__(256) void fused_kernel(
    const float* __restrict__ in, float* __restrict__ out)
{
    if (blockIdx.x < FILL_BLOCKS) {
        // ---- fill: tile the constant 36-float pattern (9 float4s) ----
        const int t = blockIdx.x * 256 + threadIdx.x;      // 0..FILL_T-1
        const int r = t % 9;                               // invariant pattern chunk
        const float4 v = reinterpret_cast<const float4*>(g_pat)[r];
        float4* __restrict__ dst =
            reinterpret_cast<float4*>(out + RES_ELEMS);
        #pragma unroll
        for (int k = 0; k < FILL_K; k++)
            dst[t + k * FILL_T] = v;                       // stride % 9 == 0
        return;
    }

    // ---- resize ----
    const int w = (blockIdx.x - FILL_BLOCKS) * 256 + threadIdx.x;
    const int j = w % OUT_W;
    const int rest = w / OUT_W;
    const int strip = rest % NSTRIPS;
    const int bc = rest / NSTRIPS;
    const int i0 = strip * STRIP;

    const float* base = in + (size_t)bc * (IN_H * IN_W);
    float* dst = out + (size_t)bc * (OUT_H * OUT_W);

    if (j >= 1 && j < OUT_W - 1)
        resize_strip<true>(base, dst, i0, j);
    else
        resize_strip<false>(base, dst, i0, j);
}

extern "C" void kernel_launch(void* const* d_in, const int* in_sizes, int n_in,
                              void* d_out, int out_size)
{
    const float* in = (const float*)d_in[0];
    float* out = (float*)d_out;
    fused_kernel<<<FILL_BLOCKS + RES_BLOCKS, 256>>>(in, out);
}

// round 4
// speedup vs baseline: 1.2592x; 1.0708x over previous
#include <cuda_runtime.h>
#include <cstdint>

// ---------------------------------------------------------------------------
// Bicubic downsample 768x768 -> 384x384 (scale exactly 0.5) + constant
// 36-weight pattern tiled into the second output. Single fused launch.
//   wn  = {-9, 29, 111, 111, 29, -9} / 262
//   pat = a_p*a_q / 68644
//   gather rows/cols: clamp(2*o - 2 + tap, 0, 767)
// ---------------------------------------------------------------------------

#define IN_H   768
#define IN_W   768
#define OUT_H  384
#define OUT_W  384
#define BC     12
#define RES_ELEMS (BC * OUT_H * OUT_W)       // 1,769,472
#define KER_BYTES (4 * OUT_H * OUT_W * 36 * 4) // 84,934,656

#define TCOLS  96                            // 4 output cols per thread
#define STRIP  8
#define NSTRIPS (OUT_H / STRIP)              // 48
#define RES_THREADS (BC * NSTRIPS * TCOLS)   // 55,296
#define RES_BLOCKS  (RES_THREADS / 256)      // 216

#define CHUNK_BYTES 36864                    // 256 pattern periods (144 B each)
#define CHUNKS_PER_FILL 4
#define FILL_BLOCKS 576                      // 576*4*36864 = KER_BYTES
#define SMEM_FLOATS (CHUNK_BYTES / 4)        // 9216

#define WN0 ((float)(-9.0  / 262.0))
#define WN1 ((float)(29.0  / 262.0))
#define WN2 ((float)(111.0 / 262.0))

#define AD(p) ((p)==0 ? -9.0 : (p)==1 ? 29.0 : (p)==2 ? 111.0 : \
               (p)==3 ? 111.0 : (p)==4 ? 29.0 : -9.0)
#define PW(p,q) ((float)(AD(p) * AD(q) / 68644.0))
#define PROW(p) PW(p,0), PW(p,1), PW(p,2), PW(p,3), PW(p,4), PW(p,5)

__device__ __constant__ __align__(16) float g_pat[36] = {
    PROW(0), PROW(1), PROW(2), PROW(3), PROW(4), PROW(5)
};

// Horizontal 6-tap filter for 4 adjacent output columns (j = 4t..4t+3).
// Loads A,B,C,D = float4 at cols {8t-4, 8t, 8t+4, 8t+8} (addresses pre-clamped
// by caller); left/right fixups reproduce the reference column clamping.
__device__ __forceinline__ float4 hfilt4(const float* __restrict__ row,
                                         int cA, int cB, int cC, int cD,
                                         bool left, bool right)
{
    float4 A = *reinterpret_cast<const float4*>(row + cA);
    float4 B = *reinterpret_cast<const float4*>(row + cB);
    float4 C = *reinterpret_cast<const float4*>(row + cC);
    float4 D = *reinterpret_cast<const float4*>(row + cD);
    if (left)  { A.z = B.x; A.w = B.x; }   // cols -2,-1 -> col 0
    if (right) { D.x = C.w; D.y = C.w; }   // cols 768,769 -> col 767
    float4 h;
    h.x = fmaf(WN0, A.z, fmaf(WN1, A.w, fmaf(WN2, B.x,
          fmaf(WN2, B.y, fmaf(WN1, B.z, WN0 * B.w)))));
    h.y = fmaf(WN0, B.x, fmaf(WN1, B.y, fmaf(WN2, B.z,
          fmaf(WN2, B.w, fmaf(WN1, C.x, WN0 * C.y)))));
    h.z = fmaf(WN0, B.z, fmaf(WN1, B.w, fmaf(WN2, C.x,
          fmaf(WN2, C.y, fmaf(WN1, C.z, WN0 * C.w)))));
    h.w = fmaf(WN0, C.x, fmaf(WN1, C.y, fmaf(WN2, C.z,
          fmaf(WN2, C.w, fmaf(WN1, D.x, WN0 * D.y)))));
    return h;
}

__device__ __forceinline__ const float* rowptr(const float* base, int r)
{
    r = r < 0 ? 0 : (r > IN_H - 1 ? IN_H - 1 : r);
    return base + r * IN_W;
}

__global__ __launch_bounds__(256) void fused_kernel(
    const float* __restrict__ in, float* __restrict__ out)
{
    __shared__ __align__(16) float spat[SMEM_FLOATS];
    const int bid = blockIdx.x;
    const int tid = threadIdx.x;

    if (bid >= RES_BLOCKS) {
        // ------------------- fill: TMA bulk stores -------------------
        const int fb = bid - RES_BLOCKS;
        // 256 threads x one 36-float period each = 9216 floats
        #pragma unroll
        for (int q = 0; q < 36; q++)
            spat[tid * 36 + q] = g_pat[q];
        __syncthreads();
        if (tid == 0) {
            asm volatile("fence.proxy.async.shared::cta;" ::: "memory");
            uint32_t saddr = (uint32_t)__cvta_generic_to_shared(spat);
            char* dst = reinterpret_cast<char*>(out + RES_ELEMS)
                      + (size_t)fb * (CHUNK_BYTES * CHUNKS_PER_FILL);
            #pragma unroll
            for (int k = 0; k < CHUNKS_PER_FILL; k++) {
                asm volatile(
                    "cp.async.bulk.global.shared::cta.bulk_group [%0], [%1], %2;"
                    :: "l"(dst + (size_t)k * CHUNK_BYTES), "r"(saddr),
                       "n"(CHUNK_BYTES) : "memory");
            }
            asm volatile("cp.async.bulk.commit_group;" ::: "memory");
            asm volatile("cp.async.bulk.wait_group 0;" ::: "memory");
        }
        return;
    }

    // ------------------- resize -------------------
    const int w     = bid * 256 + tid;
    const int t     = w % TCOLS;
    const int rest  = w / TCOLS;
    const int strip = rest % NSTRIPS;
    const int bc    = rest / NSTRIPS;
    const int i0    = strip * STRIP;

    const float* base = in + (size_t)bc * (IN_H * IN_W);
    float* dst = out + (size_t)bc * (OUT_H * OUT_W) + 4 * t;

    const bool left  = (t == 0);
    const bool right = (t == TCOLS - 1);
    const int cB = 8 * t;
    const int cC = cB + 4;
    const int cA = left  ? 0          : cB - 4;
    const int cD = right ? IN_W - 4   : cB + 8;

    const int r0 = 2 * i0 - 2;
    float4 h0 = hfilt4(rowptr(base, r0 + 0), cA, cB, cC, cD, left, right);
    float4 h1 = hfilt4(rowptr(base, r0 + 1), cA, cB, cC, cD, left, right);
    float4 h2 = hfilt4(rowptr(base, r0 + 2), cA, cB, cC, cD, left, right);
    float4 h3 = hfilt4(rowptr(base, r0 + 3), cA, cB, cC, cD, left, right);
    float4 h4 = hfilt4(rowptr(base, r0 + 4), cA, cB, cC, cD, left, right);
    float4 h5 = hfilt4(rowptr(base, r0 + 5), cA, cB, cC, cD, left, right);

    #pragma unroll
    for (int ii = 0; ii < STRIP; ii++) {
        float4 o;
        o.x = fmaf(WN0, h0.x, fmaf(WN1, h1.x, fmaf(WN2, h2.x,
              fmaf(WN2, h3.x, fmaf(WN1, h4.x, WN0 * h5.x)))));
        o.y = fmaf(WN0, h0.y, fmaf(WN1, h1.y, fmaf(WN2, h2.y,
              fmaf(WN2, h3.y, fmaf(WN1, h4.y, WN0 * h5.y)))));
        o.z = fmaf(WN0, h0.z, fmaf(WN1, h1.z, fmaf(WN2, h2.z,
              fmaf(WN2, h3.z, fmaf(WN1, h4.z, WN0 * h5.z)))));
        o.w = fmaf(WN0, h0.w, fmaf(WN1, h1.w, fmaf(WN2, h2.w,
              fmaf(WN2, h3.w, fmaf(WN1, h4.w, WN0 * h5.w)))));
        *reinterpret_cast<float4*>(dst + (size_t)(i0 + ii) * OUT_W) = o;

        if (ii < STRIP - 1) {
            h0 = h2; h1 = h3; h2 = h4; h3 = h5;
            const int rn = 2 * (i0 + ii + 1) + 2;
            h4 = hfilt4(rowptr(base, rn),     cA, cB, cC, cD, left, right);
            h5 = hfilt4(rowptr(base, rn + 1), cA, cB, cC, cD, left, right);
        }
    }
}

extern "C" void kernel_launch(void* const* d_in, const int* in_sizes, int n_in,
                              void* d_out, int out_size)
{
    const float* in = (const float*)d_in[0];
    float* out = (float*)d_out;
    fused_kernel<<<RES_BLOCKS + FILL_BLOCKS, 256>>>(in, out);
}